// round 14
// baseline (speedup 1.0000x reference)
#include <cuda_runtime.h>
#include <cstdint>

#define BB   2048
#define TT   1024
#define NW   8      // warps per CTA
#define NST  8      // stages per warp (16 rows / 2KB each)

__device__ __forceinline__ uint32_t s2u(const void* p) {
    return (uint32_t)__cvta_generic_to_shared(p);
}

// ============================ Fused decoder ================================
// One CTA (256 threads) per batch row b. Each warp owns 128 consecutive
// z rows streamed through a private 2-slot ring of 2KB chunks, loaded by
// TMA bulk copies (cp.async.bulk, one per warp-stage, issued by lane 0 with
// per-(warp,slot) mbarrier complete_tx). Data lands LINEAR in smem; reads are
// 2 lanes/row (a 2-way LDS phase conflict on 4 LDS/stage -- negligible).
// Phase B: chunked affine scan (4 timesteps/thread), combine x <- A^len*xl+x.
__global__ __launch_bounds__(256, 5)
void fused_decoder_kernel(const float* __restrict__ init_states,
                          const float* __restrict__ z,
                          const float* __restrict__ W,
                          float* __restrict__ out) {
    __shared__ alignas(16) float4 zring[NW][2][128];  // 32KB per-warp rings
    __shared__ alignas(16) float2 sv[TT];             // 8KB per-timestep vectors
    __shared__ alignas(8)  unsigned long long mbar[NW][2];
    __shared__ float2 agg[8];
    __shared__ float  sPW[5][4];
    __shared__ float4 sW0[8], sW1[8];

    const int b    = blockIdx.x;
    const int tid  = threadIdx.x;
    const int lane = tid & 31;
    const int warp = tid >> 5;

    if (tid < 64) {
        const int rr = tid >> 5, c = tid & 31;
        reinterpret_cast<float*>(rr ? sW1 : sW0)[c] = W[rr * 34 + 2 + c];
    }
    if (tid == 0) sv[0] = make_float2(init_states[2 * b], init_states[2 * b + 1]);
    if (tid < NW * 2) {
        asm volatile("mbarrier.init.shared.b64 [%0], 1;"
                     :: "r"(s2u(&mbar[tid >> 1][tid & 1])) : "memory");
    }
    __syncthreads();                         // mbarriers + sW visible

    const int rrow = lane >> 1;              // local row this lane computes
    const int half = (lane & 1) * 4;         // column half: float4s 0..3 / 4..7

    const float4* zw = reinterpret_cast<const float4*>(z)
                       + ((size_t)b * TT + warp * 128) * 8;
    const uint32_t slotu[2] = { s2u(&zring[warp][0][0]), s2u(&zring[warp][1][0]) };
    const uint32_t mbu[2]   = { s2u(&mbar[warp][0]),     s2u(&mbar[warp][1]) };

    // lane 0 only: arm barrier for 2KB and launch the bulk copy of chunk s
    auto issue = [&](int s) {
        const uint32_t mb = mbu[s & 1];
        asm volatile("mbarrier.arrive.expect_tx.shared.b64 _, [%0], %1;"
                     :: "r"(mb), "r"(2048u) : "memory");
        asm volatile("cp.async.bulk.shared::cta.global.mbarrier::complete_tx::bytes"
                     " [%0], [%1], %2, [%3];"
                     :: "r"(slotu[s & 1]), "l"(zw + s * 128), "r"(2048u), "r"(mb)
                     : "memory");
    };
    if (lane == 0) { issue(0); issue(1); }

    // acquire-wait on (warp, slot) barrier at the given phase parity
    auto wait = [&](int sl, uint32_t ph) {
        const uint32_t mb = mbu[sl];
        asm volatile(
            "{\n\t.reg .pred P;\n"
            "W%=:\n\t"
            "mbarrier.try_wait.parity.acquire.cta.shared::cta.b64 P, [%0], %1, 0x989680;\n\t"
            "@P bra D%=;\n\t"
            "bra W%=;\n"
            "D%=:\n\t}"
            :: "r"(mb), "r"(ph) : "memory");
    };

    // ---------------- Phase A: per-warp TMA-pipelined stages ----------------
    #pragma unroll 1
    for (int s = 0; s < NST; ++s) {
        wait(s & 1, (uint32_t)((s >> 1) & 1));   // chunk s landed
        const float4* slot = &zring[warp][s & 1][0];

        float px = 0.f, py = 0.f;
        #pragma unroll
        for (int k = 0; k < 4; ++k) {
            const float4 q  = slot[rrow * 8 + half + k];   // linear layout
            const float4 w0 = sW0[half + k];
            const float4 w1 = sW1[half + k];
            px = fmaf(q.x, w0.x, fmaf(q.y, w0.y, fmaf(q.z, w0.z, fmaf(q.w, w0.w, px))));
            py = fmaf(q.x, w1.x, fmaf(q.y, w1.y, fmaf(q.z, w1.z, fmaf(q.w, w1.w, py))));
        }
        // pair reduce: even lane holds px-half, odd holds py-half
        float u  = (lane & 1) ? py : px;
        float w_ = (lane & 1) ? px : py;
        u += __shfl_xor_sync(0xffffffffu, w_, 1);
        const float pv = __shfl_xor_sync(0xffffffffu, u, 1);
        const int r = warp * 128 + s * 16 + rrow;
        if (!(lane & 1) && r + 1 < TT) sv[r + 1] = make_float2(u, pv);

        __syncwarp();                        // slot fully consumed before refill
        if (lane == 0 && s + 2 < NST) issue(s + 2);
    }
    __syncthreads();                         // publish sv across warps

    // ---------------- Phase B: chunked affine scan ----------------
    const float a00 = __ldg(&W[0]),  a01 = __ldg(&W[1]);
    const float a10 = __ldg(&W[34]), a11 = __ldg(&W[35]);

    float4* svp = reinterpret_cast<float4*>(sv) + tid * 2;

    // serial inclusive scan of the 4-chunk; park results back into smem
    float2 s2;
    {
        const float4 c0 = svp[0], c1 = svp[1];
        s2 = make_float2(c0.x, c0.y);
        float s1x = fmaf(a00, s2.x, fmaf(a01, s2.y, c0.z));
        float s1y = fmaf(a10, s2.x, fmaf(a11, s2.y, c0.w));
        float s2x = fmaf(a00, s1x, fmaf(a01, s1y, c1.x));
        float s2y = fmaf(a10, s1x, fmaf(a11, s1y, c1.y));
        float s3x = fmaf(a00, s2x, fmaf(a01, s2y, c1.z));
        float s3y = fmaf(a10, s2x, fmaf(a11, s2y, c1.w));
        svp[0] = make_float4(s2.x, s2.y, s1x, s1y);
        svp[1] = make_float4(s2x, s2y, s3x, s3y);
        s2 = make_float2(s3x, s3y);
    }

    // A -> A^4 (2 squarings)
    float p00 = a00, p01 = a01, p10 = a10, p11 = a11;
    #pragma unroll
    for (int i = 0; i < 2; ++i) {
        float q00 = p00*p00 + p01*p10, q01 = p00*p01 + p01*p11;
        float q10 = p10*p00 + p11*p10, q11 = p10*p01 + p11*p11;
        p00 = q00; p01 = q01; p10 = q10; p11 = q11;
    }

    // warp shuffle scan of chunk aggregates; powers A^(4*2^d)
    float2 x = s2;
    #pragma unroll
    for (int d = 0; d < 5; ++d) {
        if (tid == 0) { sPW[d][0] = p00; sPW[d][1] = p01; sPW[d][2] = p10; sPW[d][3] = p11; }
        const int o = 1 << d;
        float ox = __shfl_up_sync(0xffffffffu, x.x, o);
        float oy = __shfl_up_sync(0xffffffffu, x.y, o);
        if (lane >= o) {
            x.x = fmaf(p00, ox, fmaf(p01, oy, x.x));
            x.y = fmaf(p10, ox, fmaf(p11, oy, x.y));
        }
        float q00 = p00*p00 + p01*p10, q01 = p00*p01 + p01*p11;
        float q10 = p10*p00 + p11*p10, q11 = p10*p01 + p11*p11;
        p00 = q00; p01 = q01; p10 = q10; p11 = q11;
    }
    // p = A^128 (one warp segment)

    if (lane == 31) agg[warp] = x;
    __syncthreads();   // publishes agg, sPW, parked chunk scans

    // prefix over earlier warps (combine power A^128), <=7 serial steps
    float2 P = make_float2(0.f, 0.f);
    for (int u = 0; u < warp; ++u) {
        float nx = fmaf(p00, P.x, fmaf(p01, P.y, agg[u].x));
        float ny = fmaf(p10, P.x, fmaf(p11, P.y, agg[u].y));
        P.x = nx; P.y = ny;
    }

    // exclusive lane prefix within warp
    float Ex = __shfl_up_sync(0xffffffffu, x.x, 1);
    float Ey = __shfl_up_sync(0xffffffffu, x.y, 1);
    if (lane == 0) { Ex = 0.f; Ey = 0.f; }

    // M = A^(4*lane) from shared power table
    float m00 = 1.f, m01 = 0.f, m10 = 0.f, m11 = 1.f;
    #pragma unroll
    for (int d = 0; d < 5; ++d) {
        if (lane & (1 << d)) {
            const float v0 = sPW[d][0], v1 = sPW[d][1];
            const float v2 = sPW[d][2], v3 = sPW[d][3];
            float n00 = v0*m00 + v1*m10, n01 = v0*m01 + v1*m11;
            float n10 = v2*m00 + v3*m10, n11 = v2*m01 + v3*m11;
            m00 = n00; m01 = n01; m10 = n10; m11 = n11;
        }
    }
    const float bx = Ex + m00 * P.x + m01 * P.y;
    const float by = Ey + m10 * P.x + m11 * P.y;

    // carry fixup on reload + coalesced streaming store
    float cx = fmaf(a00, bx, a01 * by);
    float cy = fmaf(a10, bx, a11 * by);
    const float4 r0 = svp[0], r1 = svp[1];
    float4 o0, o1;
    o0.x = r0.x + cx;  o0.y = r0.y + cy;
    { float nx = fmaf(a00, cx, a01 * cy), ny = fmaf(a10, cx, a11 * cy); cx = nx; cy = ny; }
    o0.z = r0.z + cx;  o0.w = r0.w + cy;
    { float nx = fmaf(a00, cx, a01 * cy), ny = fmaf(a10, cx, a11 * cy); cx = nx; cy = ny; }
    o1.x = r1.x + cx;  o1.y = r1.y + cy;
    { float nx = fmaf(a00, cx, a01 * cy), ny = fmaf(a10, cx, a11 * cy); cx = nx; cy = ny; }
    o1.z = r1.z + cx;  o1.w = r1.w + cy;

    float4* op = reinterpret_cast<float4*>(out) + ((size_t)b * TT / 2) + tid * 2;
    __stcs(op,     o0);
    __stcs(op + 1, o1);
}

extern "C" void kernel_launch(void* const* d_in, const int* in_sizes, int n_in,
                              void* d_out, int out_size) {
    const float* init_states = (const float*)d_in[0];
    const float* z           = (const float*)d_in[1];
    const float* W           = (const float*)d_in[2];
    float*       out         = (float*)d_out;

    fused_decoder_kernel<<<BB, 256>>>(init_states, z, W, out);
}

// round 15
// speedup vs baseline: 1.1539x; 1.1539x over previous
#include <cuda_runtime.h>
#include <cstdint>

#define BB   2048
#define TT   1024
#define NW   8      // warps per CTA
#define NST  8      // stages per warp (16 rows each)

__device__ __forceinline__ uint32_t s2u(const void* p) {
    return (uint32_t)__cvta_generic_to_shared(p);
}

// ============================ Fused decoder ================================
// One CTA (256 threads) per batch row b. Each warp owns 128 consecutive
// z rows of the batch row, streamed through a private 2-slot cp.async ring
// (2KB chunks of 16 rows). XOR-swizzled layout ((j+row)&7) makes writes and
// reads bank-conflict free. 2 lanes per row, 2 shuffles per 16 rows.
// Refill is issued at the shuffle-convergence point (all lanes' LDS reads of
// the slot have retired once pv is computed), overlapping with the sv store.
// Phase B: chunked affine scan (4 timesteps/thread), combine x <- A^len*xl+x.
__global__ __launch_bounds__(256, 5)
void fused_decoder_kernel(const float* __restrict__ init_states,
                          const float* __restrict__ z,
                          const float* __restrict__ W,
                          float* __restrict__ out) {
    __shared__ alignas(16) float4 zring[NW][2][128];  // 32KB: per-warp 2-slot rings
    __shared__ alignas(16) float2 sv[TT];             // 8KB per-timestep vectors
    __shared__ float2 agg[8];
    __shared__ float  sPW[5][4];
    __shared__ float4 sW0[8], sW1[8];

    const int b    = blockIdx.x;
    const int tid  = threadIdx.x;
    const int lane = tid & 31;
    const int warp = tid >> 5;

    if (tid < 64) {
        const int rr = tid >> 5, c = tid & 31;
        reinterpret_cast<float*>(rr ? sW1 : sW0)[c] = W[rr * 34 + 2 + c];
    }
    if (tid == 0) sv[0] = make_float2(init_states[2 * b], init_states[2 * b + 1]);

    // ---- precomputed swizzled offsets (lane-only, hoisted) ----
    int woff[4], roff[4];
    #pragma unroll
    for (int k = 0; k < 4; ++k) {            // write: linear chunk float4 i2
        const int i2 = lane + 32 * k;
        const int row = i2 >> 3, j = i2 & 7;
        woff[k] = row * 8 + ((j + row) & 7);
    }
    const int rrow = lane >> 1;              // local row this lane computes
    const int half = (lane & 1) * 4;         // chunk half: 0..3 or 4..7
    #pragma unroll
    for (int k = 0; k < 4; ++k) {
        const int c = half + k;
        roff[k] = rrow * 8 + ((c + rrow) & 7);
    }

    const float4* zw = reinterpret_cast<const float4*>(z)
                       + ((size_t)b * TT + warp * 128) * 8;
    const uint32_t slotu[2] = { s2u(&zring[warp][0][0]), s2u(&zring[warp][1][0]) };

    auto issue = [&](int s) {                // one 2KB chunk: 4 cp.async / lane
        const float4* src = zw + s * 128 + lane;
        const uint32_t dst = slotu[s & 1];
        #pragma unroll
        for (int k = 0; k < 4; ++k) {
            asm volatile("cp.async.cg.shared.global [%0], [%1], 16;"
                         :: "r"(dst + (uint32_t)woff[k] * 16u), "l"(src + 32 * k));
        }
    };

    issue(0);
    asm volatile("cp.async.commit_group;" ::: "memory");
    issue(1);
    asm volatile("cp.async.commit_group;" ::: "memory");

    __syncthreads();                         // publish sW0/sW1 (once)

    // ---------------- Phase A: per-warp pipelined stages ----------------
    #pragma unroll 1
    for (int s = 0; s < NST; ++s) {
        asm volatile("cp.async.wait_group 1;" ::: "memory");
        __syncwarp();
        const float4* slot = &zring[warp][s & 1][0];

        float px = 0.f, py = 0.f;
        #pragma unroll
        for (int k = 0; k < 4; ++k) {
            const float4 q  = slot[roff[k]];
            const float4 w0 = sW0[half + k];
            const float4 w1 = sW1[half + k];
            px = fmaf(q.x, w0.x, fmaf(q.y, w0.y, fmaf(q.z, w0.z, fmaf(q.w, w0.w, px))));
            py = fmaf(q.x, w1.x, fmaf(q.y, w1.y, fmaf(q.z, w1.z, fmaf(q.w, w1.w, py))));
        }
        // pair reduce: even lane holds px-half, odd holds py-half.
        // The full-mask shuffles are warp-convergence points, and u depends on
        // every LDS read this lane made from the slot -> after pv, ALL lanes'
        // slot reads have retired: safe to refill the slot immediately.
        float u  = (lane & 1) ? py : px;
        float w_ = (lane & 1) ? px : py;
        u += __shfl_xor_sync(0xffffffffu, w_, 1);
        const float pv = __shfl_xor_sync(0xffffffffu, u, 1);

        if (s + 2 < NST) issue(s + 2);       // early refill (slot (s+2)&1 == s&1)
        asm volatile("cp.async.commit_group;" ::: "memory");   // uniform count

        const float r = warp * 128 + s * 16 + rrow;
        const int ri = warp * 128 + s * 16 + rrow;
        (void)r;
        if (!(lane & 1) && ri + 1 < TT) sv[ri + 1] = make_float2(u, pv);
    }
    __syncthreads();                         // publish sv across warps

    // ---------------- Phase B: chunked affine scan ----------------
    const float a00 = __ldg(&W[0]),  a01 = __ldg(&W[1]);
    const float a10 = __ldg(&W[34]), a11 = __ldg(&W[35]);

    float4* svp = reinterpret_cast<float4*>(sv) + tid * 2;

    // serial inclusive scan of the 4-chunk; park results back into smem
    float2 s2;
    {
        const float4 c0 = svp[0], c1 = svp[1];
        s2 = make_float2(c0.x, c0.y);
        float s1x = fmaf(a00, s2.x, fmaf(a01, s2.y, c0.z));
        float s1y = fmaf(a10, s2.x, fmaf(a11, s2.y, c0.w));
        float s2x = fmaf(a00, s1x, fmaf(a01, s1y, c1.x));
        float s2y = fmaf(a10, s1x, fmaf(a11, s1y, c1.y));
        float s3x = fmaf(a00, s2x, fmaf(a01, s2y, c1.z));
        float s3y = fmaf(a10, s2x, fmaf(a11, s2y, c1.w));
        svp[0] = make_float4(s2.x, s2.y, s1x, s1y);
        svp[1] = make_float4(s2x, s2y, s3x, s3y);
        s2 = make_float2(s3x, s3y);
    }

    // A -> A^4 (2 squarings)
    float p00 = a00, p01 = a01, p10 = a10, p11 = a11;
    #pragma unroll
    for (int i = 0; i < 2; ++i) {
        float q00 = p00*p00 + p01*p10, q01 = p00*p01 + p01*p11;
        float q10 = p10*p00 + p11*p10, q11 = p10*p01 + p11*p11;
        p00 = q00; p01 = q01; p10 = q10; p11 = q11;
    }

    // warp shuffle scan of chunk aggregates; powers A^(4*2^d)
    float2 x = s2;
    #pragma unroll
    for (int d = 0; d < 5; ++d) {
        if (tid == 0) { sPW[d][0] = p00; sPW[d][1] = p01; sPW[d][2] = p10; sPW[d][3] = p11; }
        const int o = 1 << d;
        float ox = __shfl_up_sync(0xffffffffu, x.x, o);
        float oy = __shfl_up_sync(0xffffffffu, x.y, o);
        if (lane >= o) {
            x.x = fmaf(p00, ox, fmaf(p01, oy, x.x));
            x.y = fmaf(p10, ox, fmaf(p11, oy, x.y));
        }
        float q00 = p00*p00 + p01*p10, q01 = p00*p01 + p01*p11;
        float q10 = p10*p00 + p11*p10, q11 = p10*p01 + p11*p11;
        p00 = q00; p01 = q01; p10 = q10; p11 = q11;
    }
    // p = A^128 (one warp segment)

    if (lane == 31) agg[warp] = x;
    __syncthreads();   // publishes agg, sPW, parked chunk scans

    // prefix over earlier warps (combine power A^128), <=7 serial steps
    float2 P = make_float2(0.f, 0.f);
    for (int u = 0; u < warp; ++u) {
        float nx = fmaf(p00, P.x, fmaf(p01, P.y, agg[u].x));
        float ny = fmaf(p10, P.x, fmaf(p11, P.y, agg[u].y));
        P.x = nx; P.y = ny;
    }

    // exclusive lane prefix within warp
    float Ex = __shfl_up_sync(0xffffffffu, x.x, 1);
    float Ey = __shfl_up_sync(0xffffffffu, x.y, 1);
    if (lane == 0) { Ex = 0.f; Ey = 0.f; }

    // M = A^(4*lane) from shared power table
    float m00 = 1.f, m01 = 0.f, m10 = 0.f, m11 = 1.f;
    #pragma unroll
    for (int d = 0; d < 5; ++d) {
        if (lane & (1 << d)) {
            const float v0 = sPW[d][0], v1 = sPW[d][1];
            const float v2 = sPW[d][2], v3 = sPW[d][3];
            float n00 = v0*m00 + v1*m10, n01 = v0*m01 + v1*m11;
            float n10 = v2*m00 + v3*m10, n11 = v2*m01 + v3*m11;
            m00 = n00; m01 = n01; m10 = n10; m11 = n11;
        }
    }
    const float bx = Ex + m00 * P.x + m01 * P.y;
    const float by = Ey + m10 * P.x + m11 * P.y;

    // carry fixup on reload + coalesced streaming store
    float cx = fmaf(a00, bx, a01 * by);
    float cy = fmaf(a10, bx, a11 * by);
    const float4 r0 = svp[0], r1 = svp[1];
    float4 o0, o1;
    o0.x = r0.x + cx;  o0.y = r0.y + cy;
    { float nx = fmaf(a00, cx, a01 * cy), ny = fmaf(a10, cx, a11 * cy); cx = nx; cy = ny; }
    o0.z = r0.z + cx;  o0.w = r0.w + cy;
    { float nx = fmaf(a00, cx, a01 * cy), ny = fmaf(a10, cx, a11 * cy); cx = nx; cy = ny; }
    o1.x = r1.x + cx;  o1.y = r1.y + cy;
    { float nx = fmaf(a00, cx, a01 * cy), ny = fmaf(a10, cx, a11 * cy); cx = nx; cy = ny; }
    o1.z = r1.z + cx;  o1.w = r1.w + cy;

    float4* op = reinterpret_cast<float4*>(out) + ((size_t)b * TT / 2) + tid * 2;
    __stcs(op,     o0);
    __stcs(op + 1, o1);
}

extern "C" void kernel_launch(void* const* d_in, const int* in_sizes, int n_in,
                              void* d_out, int out_size) {
    const float* init_states = (const float*)d_in[0];
    const float* z           = (const float*)d_in[1];
    const float* W           = (const float*)d_in[2];
    float*       out         = (float*)d_out;

    fused_decoder_kernel<<<BB, 256>>>(init_states, z, W, out);
}

// round 16
// speedup vs baseline: 1.1643x; 1.0090x over previous
#include <cuda_runtime.h>
#include <cstdint>

#define BB   2048
#define TT   1024
#define NW   8      // warps per CTA
#define NST  8      // stages per warp (16 rows each)

__device__ __forceinline__ uint32_t s2u(const void* p) {
    return (uint32_t)__cvta_generic_to_shared(p);
}

// ============================ Fused decoder (final) ========================
// One CTA (256 threads) per batch row b. Each warp owns 128 consecutive
// z rows, streamed through a private 2-slot cp.async ring (2KB chunks of
// 16 rows, XOR-swizzled -> conflict-free writes AND reads). 2 lanes per row,
// 2 shuffles per 16 rows; warp-local sync only in phase A.
// cp.async carries an .L2::256B prefetch hint (warp pattern is 2KB contiguous).
// Phase B: chunked affine scan (4 timesteps/thread), combine x <- A^len*xl+x,
// chunk-scanned values parked in smem, carry fixup on reload, float4 stores.
__global__ __launch_bounds__(256, 5)
void fused_decoder_kernel(const float* __restrict__ init_states,
                          const float* __restrict__ z,
                          const float* __restrict__ W,
                          float* __restrict__ out) {
    __shared__ alignas(16) float4 zring[NW][2][128];  // 32KB: per-warp 2-slot rings
    __shared__ alignas(16) float2 sv[TT];             // 8KB per-timestep vectors
    __shared__ float2 agg[8];
    __shared__ float  sPW[5][4];
    __shared__ float4 sW0[8], sW1[8];

    const int b    = blockIdx.x;
    const int tid  = threadIdx.x;
    const int lane = tid & 31;
    const int warp = tid >> 5;

    if (tid < 64) {
        const int rr = tid >> 5, c = tid & 31;
        reinterpret_cast<float*>(rr ? sW1 : sW0)[c] = W[rr * 34 + 2 + c];
    }
    if (tid == 0) sv[0] = make_float2(init_states[2 * b], init_states[2 * b + 1]);

    // ---- precomputed swizzled offsets (lane-only, hoisted) ----
    int woff[4], roff[4];
    #pragma unroll
    for (int k = 0; k < 4; ++k) {            // write: linear chunk float4 i2
        const int i2 = lane + 32 * k;
        const int row = i2 >> 3, j = i2 & 7;
        woff[k] = row * 8 + ((j + row) & 7);
    }
    const int rrow = lane >> 1;              // local row this lane computes
    const int half = (lane & 1) * 4;         // chunk half: 0..3 or 4..7
    #pragma unroll
    for (int k = 0; k < 4; ++k) {
        const int c = half + k;
        roff[k] = rrow * 8 + ((c + rrow) & 7);
    }

    const float4* zw = reinterpret_cast<const float4*>(z)
                       + ((size_t)b * TT + warp * 128) * 8;
    const uint32_t slotu[2] = { s2u(&zring[warp][0][0]), s2u(&zring[warp][1][0]) };

    auto issue = [&](int s) {                // one 2KB chunk: 4 cp.async / lane
        const float4* src = zw + s * 128 + lane;
        const uint32_t dst = slotu[s & 1];
        #pragma unroll
        for (int k = 0; k < 4; ++k) {
            asm volatile("cp.async.cg.shared.global.L2::256B [%0], [%1], 16;"
                         :: "r"(dst + (uint32_t)woff[k] * 16u), "l"(src + 32 * k));
        }
    };

    issue(0);
    asm volatile("cp.async.commit_group;" ::: "memory");
    issue(1);
    asm volatile("cp.async.commit_group;" ::: "memory");

    __syncthreads();                         // publish sW0/sW1 (once)

    // ---------------- Phase A: per-warp pipelined stages ----------------
    #pragma unroll 1
    for (int s = 0; s < NST; ++s) {
        asm volatile("cp.async.wait_group 1;" ::: "memory");
        __syncwarp();                        // cross-lane visibility of chunk s
        const float4* slot = &zring[warp][s & 1][0];

        float px = 0.f, py = 0.f;
        #pragma unroll
        for (int k = 0; k < 4; ++k) {
            const float4 q  = slot[roff[k]];
            const float4 w0 = sW0[half + k];
            const float4 w1 = sW1[half + k];
            px = fmaf(q.x, w0.x, fmaf(q.y, w0.y, fmaf(q.z, w0.z, fmaf(q.w, w0.w, px))));
            py = fmaf(q.x, w1.x, fmaf(q.y, w1.y, fmaf(q.z, w1.z, fmaf(q.w, w1.w, py))));
        }
        // pair reduce: even lane holds px-half, odd holds py-half
        float u  = (lane & 1) ? py : px;
        float w_ = (lane & 1) ? px : py;
        u += __shfl_xor_sync(0xffffffffu, w_, 1);
        const float pv = __shfl_xor_sync(0xffffffffu, u, 1);
        const int r = warp * 128 + s * 16 + rrow;
        if (!(lane & 1) && r + 1 < TT) sv[r + 1] = make_float2(u, pv);

        __syncwarp();                        // slot fully consumed before refill
        if (s + 2 < NST) issue(s + 2);
        asm volatile("cp.async.commit_group;" ::: "memory");   // uniform count
    }
    __syncthreads();                         // publish sv across warps

    // ---------------- Phase B: chunked affine scan ----------------
    const float a00 = __ldg(&W[0]),  a01 = __ldg(&W[1]);
    const float a10 = __ldg(&W[34]), a11 = __ldg(&W[35]);

    float4* svp = reinterpret_cast<float4*>(sv) + tid * 2;

    // serial inclusive scan of the 4-chunk; park results back into smem
    float2 s2;
    {
        const float4 c0 = svp[0], c1 = svp[1];
        s2 = make_float2(c0.x, c0.y);
        float s1x = fmaf(a00, s2.x, fmaf(a01, s2.y, c0.z));
        float s1y = fmaf(a10, s2.x, fmaf(a11, s2.y, c0.w));
        float s2x = fmaf(a00, s1x, fmaf(a01, s1y, c1.x));
        float s2y = fmaf(a10, s1x, fmaf(a11, s1y, c1.y));
        float s3x = fmaf(a00, s2x, fmaf(a01, s2y, c1.z));
        float s3y = fmaf(a10, s2x, fmaf(a11, s2y, c1.w));
        svp[0] = make_float4(s2.x, s2.y, s1x, s1y);
        svp[1] = make_float4(s2x, s2y, s3x, s3y);
        s2 = make_float2(s3x, s3y);
    }

    // A -> A^4 (2 squarings)
    float p00 = a00, p01 = a01, p10 = a10, p11 = a11;
    #pragma unroll
    for (int i = 0; i < 2; ++i) {
        float q00 = p00*p00 + p01*p10, q01 = p00*p01 + p01*p11;
        float q10 = p10*p00 + p11*p10, q11 = p10*p01 + p11*p11;
        p00 = q00; p01 = q01; p10 = q10; p11 = q11;
    }

    // warp shuffle scan of chunk aggregates; powers A^(4*2^d)
    float2 x = s2;
    #pragma unroll
    for (int d = 0; d < 5; ++d) {
        if (tid == 0) { sPW[d][0] = p00; sPW[d][1] = p01; sPW[d][2] = p10; sPW[d][3] = p11; }
        const int o = 1 << d;
        float ox = __shfl_up_sync(0xffffffffu, x.x, o);
        float oy = __shfl_up_sync(0xffffffffu, x.y, o);
        if (lane >= o) {
            x.x = fmaf(p00, ox, fmaf(p01, oy, x.x));
            x.y = fmaf(p10, ox, fmaf(p11, oy, x.y));
        }
        float q00 = p00*p00 + p01*p10, q01 = p00*p01 + p01*p11;
        float q10 = p10*p00 + p11*p10, q11 = p10*p01 + p11*p11;
        p00 = q00; p01 = q01; p10 = q10; p11 = q11;
    }
    // p = A^128 (one warp segment)

    if (lane == 31) agg[warp] = x;
    __syncthreads();   // publishes agg, sPW, parked chunk scans

    // prefix over earlier warps (combine power A^128), <=7 serial steps
    float2 P = make_float2(0.f, 0.f);
    for (int u = 0; u < warp; ++u) {
        float nx = fmaf(p00, P.x, fmaf(p01, P.y, agg[u].x));
        float ny = fmaf(p10, P.x, fmaf(p11, P.y, agg[u].y));
        P.x = nx; P.y = ny;
    }

    // exclusive lane prefix within warp
    float Ex = __shfl_up_sync(0xffffffffu, x.x, 1);
    float Ey = __shfl_up_sync(0xffffffffu, x.y, 1);
    if (lane == 0) { Ex = 0.f; Ey = 0.f; }

    // M = A^(4*lane) from shared power table
    float m00 = 1.f, m01 = 0.f, m10 = 0.f, m11 = 1.f;
    #pragma unroll
    for (int d = 0; d < 5; ++d) {
        if (lane & (1 << d)) {
            const float v0 = sPW[d][0], v1 = sPW[d][1];
            const float v2 = sPW[d][2], v3 = sPW[d][3];
            float n00 = v0*m00 + v1*m10, n01 = v0*m01 + v1*m11;
            float n10 = v2*m00 + v3*m10, n11 = v2*m01 + v3*m11;
            m00 = n00; m01 = n01; m10 = n10; m11 = n11;
        }
    }
    const float bx = Ex + m00 * P.x + m01 * P.y;
    const float by = Ey + m10 * P.x + m11 * P.y;

    // carry fixup on reload + coalesced streaming store
    float cx = fmaf(a00, bx, a01 * by);
    float cy = fmaf(a10, bx, a11 * by);
    const float4 r0 = svp[0], r1 = svp[1];
    float4 o0, o1;
    o0.x = r0.x + cx;  o0.y = r0.y + cy;
    { float nx = fmaf(a00, cx, a01 * cy), ny = fmaf(a10, cx, a11 * cy); cx = nx; cy = ny; }
    o0.z = r0.z + cx;  o0.w = r0.w + cy;
    { float nx = fmaf(a00, cx, a01 * cy), ny = fmaf(a10, cx, a11 * cy); cx = nx; cy = ny; }
    o1.x = r1.x + cx;  o1.y = r1.y + cy;
    { float nx = fmaf(a00, cx, a01 * cy), ny = fmaf(a10, cx, a11 * cy); cx = nx; cy = ny; }
    o1.z = r1.z + cx;  o1.w = r1.w + cy;

    float4* op = reinterpret_cast<float4*>(out) + ((size_t)b * TT / 2) + tid * 2;
    __stcs(op,     o0);
    __stcs(op + 1, o1);
}

extern "C" void kernel_launch(void* const* d_in, const int* in_sizes, int n_in,
                              void* d_out, int out_size) {
    const float* init_states = (const float*)d_in[0];
    const float* z           = (const float*)d_in[1];
    const float* W           = (const float*)d_in[2];
    float*       out         = (float*)d_out;

    fused_decoder_kernel<<<BB, 256>>>(init_states, z, W, out);
}